// round 14
// baseline (speedup 1.0000x reference)
#include <cuda_runtime.h>

// SSKernelDiag: out[h,l] = 2 * Re( sum_n Cc[h,n] * A[h,n]^l )
//   A = exp(abslog + i*phase), dtA = abslog + i*phase, Cc = C*(A-1)/dtA
// H=256, N=64, L=4096, CH=1.
//
// R14: transcendental-minimal prologue. Only phase 1 uses exp/sincos (3 MUFU
// per n). Per-rank binary power table A^{8,16,24,32,64,128,256,512} built by
// cmul chains; sQr (conj A^t) and W anchors/steps are pure cmul products.
// Decay truncation with rank-sorted n; PARTS=2; first 8 ranks' q cached in
// registers so most tiles run 2 LDS.128 + 8 FFMA2 with zero q loads.

#define HH 256
#define NN 64
#define LL 4096
#define TILE 32
#define PARTS 2
#define JT 64              // tiles per block
#define NTHREADS 256
#define NWARPS 8
#define KPW 8              // tiles per warp
#define CUT 23.0f          // e^-23 ~ 1e-10 magnitude cutoff

typedef unsigned long long ull;

__device__ __forceinline__ float2 cmul(float2 a, float2 b) {
    return make_float2(fmaf(a.x, b.x, -(a.y * b.y)),
                       fmaf(a.x, b.y,  (a.y * b.x)));
}
__device__ __forceinline__ ull pack2(float x, float y) {
    ull r;
    asm("mov.b64 %0, {%1, %2};" : "=l"(r) : "f"(x), "f"(y));
    return r;
}
__device__ __forceinline__ float2 unpack2(ull v) {
    float x, y;
    asm("mov.b64 {%0, %1}, %2;" : "=f"(x), "=f"(y) : "l"(v));
    return make_float2(x, y);
}
__device__ __forceinline__ void ffma2(ull& acc, ull a, ull b) {
    asm("fma.rn.f32x2 %0, %1, %2, %0;" : "+l"(acc) : "l"(a), "l"(b));
}
__device__ __forceinline__ ull fadd2(ull a, ull b) {
    ull r;
    asm("add.rn.f32x2 %0, %1, %2;" : "=l"(r) : "l"(a), "l"(b));
    return r;
}

__global__ void __launch_bounds__(NTHREADS)
ssk_diag_kernel(const float* __restrict__ abslog,
                const float* __restrict__ phase,
                const float* __restrict__ C,
                float* __restrict__ out) {
    __shared__ float2 AR[NN];               // rank-indexed A
    __shared__ float2 CcR[NN];              // rank-indexed 2*Cc
    __shared__ float2 pw[NN][8];            // A^{8,16,24,32,64,128,256,512}
    __shared__ int    lcut[NN];
    __shared__ int    scnt[JT];
    __shared__ float2 sQr[NN][TILE];        // 16 KB: conj-packed A^t, rank idx
    __shared__ float2 sWbuf[NWARPS][NN];    // 4 KB: per-warp W staging

    const int bid  = blockIdx.x;
    const int h    = bid >> 1;
    const int part = bid & 1;
    const int tid  = threadIdx.x;
    const int warp = tid >> 5;
    const int lane = tid & 31;

    // ---- phase 1 (tid<64): load params, A = exp(dtA), lcut ----
    float al = 0.f, ph = 0.f;
    float2 Av  = make_float2(0.f, 0.f);
    float2 Cin = make_float2(0.f, 0.f);
    if (tid < NN) {
        al  = abslog[h * NN + tid];
        ph  = phase[h * NN + tid];
        Cin = reinterpret_cast<const float2*>(C)[h * NN + tid];
        float er = __expf(al);
        float s0, c0;
        __sincosf(ph, &s0, &c0);
        Av = make_float2(er * c0, er * s0);
        lcut[tid] = (int)fminf((float)LL, CUT / (-al) + 1.0f);
    }
    __syncthreads();

    // ---- phase 2: rank + Cc + binary power chain (0..63) | counts (64..127)
    if (tid < NN) {
        const int my = lcut[tid];
        int rank = 0;
        #pragma unroll 8
        for (int m = 0; m < NN; m++) {
            const int o = lcut[m];
            rank += (o > my) || (o == my && m < tid);
        }
        // 2*Cc = 2*C*(A-1)/dtA
        float2 Am1 = make_float2(Av.x - 1.0f, Av.y);
        float2 num = cmul(Cin, Am1);
        float  inv = 1.0f / fmaf(al, al, ph * ph);
        AR[rank]  = Av;
        CcR[rank] = make_float2(2.0f * (num.x * al + num.y * ph) * inv,
                                2.0f * (num.y * al - num.x * ph) * inv);
        // power chain (10 cmuls): A2,A4,A8,A16,A24,A32,A64,A128,A256,A512
        float2 A2   = cmul(Av, Av);
        float2 A4   = cmul(A2, A2);
        float2 A8   = cmul(A4, A4);
        float2 A16  = cmul(A8, A8);
        float2 A24  = cmul(A16, A8);
        float2 A32  = cmul(A16, A16);
        float2 A64  = cmul(A32, A32);
        float2 A128 = cmul(A64, A64);
        float2 A256 = cmul(A128, A128);
        float2 A512 = cmul(A256, A256);
        pw[rank][0] = A8;   pw[rank][1] = A16;
        pw[rank][2] = A24;  pw[rank][3] = A32;
        pw[rank][4] = A64;  pw[rank][5] = A128;
        pw[rank][6] = A256; pw[rank][7] = A512;
    } else if (tid < NN + JT) {
        const int j = tid - NN;
        const int lmin = TILE * (part + PARTS * j);
        int c = 0;
        #pragma unroll 8
        for (int m = 0; m < NN; m++) c += (lcut[m] > lmin);
        scnt[j] = (c + 3) & ~3;
    }
    __syncthreads();

    // ---- phase 3a: sQr[r][t] = conj-packed A^t ; thread = (r, q8) ----
    {
        const int r  = tid & 63;
        const int q8 = tid >> 6;             // [0,4)
        float2 A1 = AR[r];
        float2 P  = (q8 == 0) ? make_float2(1.0f, 0.0f) : pw[r][q8 - 1];
        #pragma unroll
        for (int j = 0; j < 8; j++) {
            sQr[r][8 * q8 + j] = make_float2(P.x, -P.y);
            P = cmul(P, A1);
        }
    }
    // ---- phase 3b: W state per lane (ranks lane, lane+32), no MUFU ----
    // first tile index idx = part + 2*warp in [0,15]; anchor A^(32*idx) from
    // binary decomposition over {A32,A64,A128,A256}; step S = A^512.
    float2 W0, W1, S0, S1;
    {
        const int idx = part + PARTS * warp;
        float2 E0 = make_float2(1.0f, 0.0f);
        float2 E1 = make_float2(1.0f, 0.0f);
        #pragma unroll
        for (int b = 0; b < 4; b++) {
            if ((idx >> b) & 1) {
                E0 = cmul(E0, pw[lane][3 + b]);
                E1 = cmul(E1, pw[lane + 32][3 + b]);
            }
        }
        W0 = cmul(CcR[lane],      E0);
        W1 = cmul(CcR[lane + 32], E1);
        S0 = pw[lane][7];
        S1 = pw[lane + 32][7];
    }
    __syncthreads();

    // ---- cache first 8 ranks' q in registers ----
    ull qr[8];
    #pragma unroll
    for (int i = 0; i < 8; i++)
        qr[i] = *reinterpret_cast<const ull*>(&sQr[i][lane]);

    // ---- main: 8 tiles per warp; j = warp + 8k, tl = part + 2j ----
    float* outh = out + h * LL;
    const ulonglong2* wb = reinterpret_cast<const ulonglong2*>(sWbuf[warp]);

    #pragma unroll
    for (int k = 0; k < KPW; k++) {
        const int j  = warp + NWARPS * k;
        const int tl = part + PARTS * j;
        __syncwarp();
        sWbuf[warp][lane]      = W0;
        sWbuf[warp][lane + 32] = W1;
        __syncwarp();

        const int m = scnt[j];
        ull acc0 = pack2(0.0f, 0.0f);
        ull acc1 = acc0;
        if (m > 0) {
            ulonglong2 wa = wb[0], wc = wb[1];
            ffma2(acc0, wa.x, qr[0]); ffma2(acc1, wa.y, qr[1]);
            ffma2(acc0, wc.x, qr[2]); ffma2(acc1, wc.y, qr[3]);
            if (m > 4) {
                wa = wb[2]; wc = wb[3];
                ffma2(acc0, wa.x, qr[4]); ffma2(acc1, wa.y, qr[5]);
                ffma2(acc0, wc.x, qr[6]); ffma2(acc1, wc.y, qr[7]);
                for (int r = 8; r < m; r += 4) {
                    ulonglong2 w0 = wb[(r >> 1)];
                    ulonglong2 w1 = wb[(r >> 1) + 1];
                    ull q0 = *reinterpret_cast<const ull*>(&sQr[r + 0][lane]);
                    ull q1 = *reinterpret_cast<const ull*>(&sQr[r + 1][lane]);
                    ull q2 = *reinterpret_cast<const ull*>(&sQr[r + 2][lane]);
                    ull q3 = *reinterpret_cast<const ull*>(&sQr[r + 3][lane]);
                    ffma2(acc0, w0.x, q0);
                    ffma2(acc1, w0.y, q1);
                    ffma2(acc0, w1.x, q2);
                    ffma2(acc1, w1.y, q3);
                }
            }
        }
        float2 u = unpack2(fadd2(acc0, acc1));
        outh[TILE * tl + lane] = u.x + u.y;

        W0 = cmul(W0, S0);
        W1 = cmul(W1, S1);
    }
}

extern "C" void kernel_launch(void* const* d_in, const int* in_sizes, int n_in,
                              void* d_out, int out_size) {
    const float* abslog = (const float*)d_in[0];  // (H, N) f32
    const float* phase  = (const float*)d_in[1];  // (H, N) f32
    const float* C      = (const float*)d_in[2];  // (1, H, N, 2) f32
    float* out = (float*)d_out;                   // (1, H, L) f32

    ssk_diag_kernel<<<HH * PARTS, NTHREADS>>>(abslog, phase, C, out);
}